// round 1
// baseline (speedup 1.0000x reference)
#include <cuda_runtime.h>
#include <math.h>

// Problem constants
#define Bc   32     // batch
#define Tc   256    // time / image width W
#define Fc   32     // features / image height H
#define HIDc 128
#define ZW   640    // 5*HID
#define Vc   101    // VOCAB+1
#define Sc   65     // 2*LBL+1
#define LBLc 32
#define NEGF (-1e30f)

// ---------------------------------------------------------------------------
// Device scratch (no allocations allowed). Double-buffered row state by
// diagonal parity: value written at diagonal d is read only at d+1.
// ---------------------------------------------------------------------------
__device__ float g_h[2][Fc][Bc][HIDc];     // [parity][row h][batch][k]
__device__ float g_c[2][Fc][Bc][HIDc];
__device__ float g_feat[Bc][Tc][HIDc];     // sum over height h (written in-place)
__device__ float g_logp[Bc][Tc][Vc];

__device__ __forceinline__ float sigf(float x) { return 1.0f / (1.0f + expf(-x)); }

// ---------------------------------------------------------------------------
// Zero the recurrent state buffers (both parities). feat needs no init:
// cell h==0 writes (=), h>0 accumulates (+=), and h==0 exists for every w.
// ---------------------------------------------------------------------------
__global__ void init_kernel() {
    const int n = 2 * Fc * Bc * HIDc;
    float* ph = &g_h[0][0][0][0];
    float* pc = &g_c[0][0][0][0];
    for (int i = blockIdx.x * blockDim.x + threadIdx.x; i < n;
         i += gridDim.x * blockDim.x) {
        ph[i] = 0.0f;
        pc[i] = 0.0f;
    }
}

// ---------------------------------------------------------------------------
// One anti-diagonal d of the 2D LSTM. Cells (w = d-h, h), h in [h_lo, h_hi].
// Grid: (ncells, 4 batch-groups), 320 threads.
// Each CTA: one cell, 8 batch rows, all 640 z-columns.
// Thread t owns columns n0 = t, n1 = t + 320 for all 8 rows.
// ---------------------------------------------------------------------------
__global__ __launch_bounds__(320)
void diag_kernel(int d,
                 const float* __restrict__ X,     // [B,T,F]
                 const float* __restrict__ Wx,    // [1,640]
                 const float* __restrict__ Wh1,   // [128,640]
                 const float* __restrict__ Wh2,   // [128,640]
                 const float* __restrict__ bias)  // [640]
{
    const int h_lo = (d > Tc - 1) ? (d - (Tc - 1)) : 0;
    const int h    = h_lo + blockIdx.x;
    const int w    = d - h;
    const int bg   = blockIdx.y;            // batch group: 8 batches
    const int tid  = threadIdx.x;           // 0..319
    const int rd   = (d + 1) & 1;           // read parity  (== (d-1)&1)
    const int wr   = d & 1;                 // write parity

    __shared__ float s_hl[8][HIDc];          // h_left  (row h state from d-1)
    __shared__ float s_hu[8][HIDc];          // h_up    (row h-1 state from d-1)
    __shared__ float s_z[8][ZW];

    for (int i = tid; i < 8 * HIDc; i += 320) {
        int r = i >> 7, k = i & (HIDc - 1);
        int b = bg * 8 + r;
        s_hl[r][k] = g_h[rd][h][b][k];                       // zero-init covers w==0
        s_hu[r][k] = (h > 0) ? g_h[rd][h - 1][b][k] : 0.0f;
    }
    __syncthreads();

    const int n0 = tid, n1 = tid + 320;
    float acc0[8], acc1[8];
    {
        const float wx0 = Wx[n0], wx1 = Wx[n1];
        const float b0 = bias[n0], b1 = bias[n1];
#pragma unroll
        for (int r = 0; r < 8; r++) {
            int b = bg * 8 + r;
            float xv = X[b * (Tc * Fc) + w * Fc + h];
            acc0[r] = fmaf(xv, wx0, b0);
            acc1[r] = fmaf(xv, wx1, b1);
        }
    }

#pragma unroll 4
    for (int k = 0; k < HIDc; k++) {
        const float w0 = Wh1[k * ZW + n0];
        const float w1 = Wh1[k * ZW + n1];
#pragma unroll
        for (int r = 0; r < 8; r++) {
            float hv = s_hl[r][k];
            acc0[r] = fmaf(hv, w0, acc0[r]);
            acc1[r] = fmaf(hv, w1, acc1[r]);
        }
    }
#pragma unroll 4
    for (int k = 0; k < HIDc; k++) {
        const float w0 = Wh2[k * ZW + n0];
        const float w1 = Wh2[k * ZW + n1];
#pragma unroll
        for (int r = 0; r < 8; r++) {
            float hv = s_hu[r][k];
            acc0[r] = fmaf(hv, w0, acc0[r]);
            acc1[r] = fmaf(hv, w1, acc1[r]);
        }
    }

#pragma unroll
    for (int r = 0; r < 8; r++) {
        s_z[r][n0] = acc0[r];
        s_z[r][n1] = acc1[r];
    }
    __syncthreads();

    // Gates: z = [i | g | f1 | f2 | o], each 128 wide.
    for (int i = tid; i < 8 * HIDc; i += 320) {
        int r = i >> 7, k = i & (HIDc - 1);
        int b = bg * 8 + r;
        float zi  = s_z[r][k];
        float zg  = s_z[r][k + 128];
        float zf1 = s_z[r][k + 256];
        float zf2 = s_z[r][k + 384];
        float zo  = s_z[r][k + 512];
        float cl  = g_c[rd][h][b][k];
        float cu  = (h > 0) ? g_c[rd][h - 1][b][k] : 0.0f;
        float c   = sigf(zf1) * cl + sigf(zf2) * cu + sigf(zi) * tanhf(zg);
        float hh  = sigf(zo) * tanhf(c);
        g_c[wr][h][b][k] = c;
        g_h[wr][h][b][k] = hh;
        float* fp = &g_feat[b][w][k];
        if (h == 0) *fp = hh; else *fp = *fp + hh;
    }
}

// ---------------------------------------------------------------------------
// logits = feat @ W_fc + b_fc ; logp = log_softmax(logits)
// One block per (w, b). 128 threads; thread n < 101 owns one vocab column.
// ---------------------------------------------------------------------------
__global__ __launch_bounds__(128)
void fc_kernel(const float* __restrict__ W_fc,   // [128,101]
               const float* __restrict__ b_fc)   // [101]
{
    const int w = blockIdx.x, b = blockIdx.y, tid = threadIdx.x;
    __shared__ float s_f[HIDc];
    __shared__ float red[128];

    s_f[tid] = g_feat[b][w][tid];
    __syncthreads();

    float logit = 0.0f;
    if (tid < Vc) {
        float a = b_fc[tid];
#pragma unroll 4
        for (int k = 0; k < HIDc; k++) a = fmaf(s_f[k], W_fc[k * Vc + tid], a);
        logit = a;
    }

    // max
    red[tid] = (tid < Vc) ? logit : -INFINITY;
    __syncthreads();
#pragma unroll
    for (int s = 64; s > 0; s >>= 1) {
        if (tid < s) red[tid] = fmaxf(red[tid], red[tid + s]);
        __syncthreads();
    }
    const float m = red[0];
    __syncthreads();

    // sum exp
    red[tid] = (tid < Vc) ? expf(logit - m) : 0.0f;
    __syncthreads();
#pragma unroll
    for (int s = 64; s > 0; s >>= 1) {
        if (tid < s) red[tid] += red[tid + s];
        __syncthreads();
    }
    const float lse = m + logf(red[0]);

    if (tid < Vc) g_logp[b][w][tid] = logit - lse;
}

// ---------------------------------------------------------------------------
// CTC forward (alpha recursion). One block per batch; thread s < 65 owns one
// extended-label state.
// ---------------------------------------------------------------------------
__global__ __launch_bounds__(128)
void ctc_kernel(const int* __restrict__ y, float* __restrict__ out)
{
    const int b = blockIdx.x, tid = threadIdx.x;
    __shared__ float alpha[Sc];
    __shared__ int   ext[Sc];

    if (tid < Sc) {
        ext[tid] = (tid & 1) ? y[b * LBLc + (tid >> 1)] : (Vc - 1);  // blank=100
    }
    __syncthreads();

    bool sk = false;
    if (tid < Sc) {
        sk = (tid >= 2) && (ext[tid] != (Vc - 1)) && (ext[tid] != ext[tid - 2]);
        float a0;
        if (tid == 0)      a0 = g_logp[b][0][ext[0]];
        else if (tid == 1) a0 = g_logp[b][0][ext[1]];
        else               a0 = NEGF;
        alpha[tid] = a0;
    }
    __syncthreads();

    for (int t = 1; t < Tc; t++) {
        float nv = NEGF;
        if (tid < Sc) {
            float a0 = alpha[tid];
            float a1 = (tid >= 1) ? alpha[tid - 1] : NEGF;
            float a2 = sk ? alpha[tid - 2] : NEGF;
            float m  = fmaxf(a0, fmaxf(a1, a2));
            float lse = m + logf(expf(a0 - m) + expf(a1 - m) + expf(a2 - m));
            nv = lse + g_logp[b][t][ext[tid]];
        }
        __syncthreads();
        if (tid < Sc) alpha[tid] = nv;
        __syncthreads();
    }

    if (tid == 0) {
        float a = alpha[Sc - 1], c = alpha[Sc - 2];
        float m = fmaxf(a, c);
        out[b] = -(m + logf(expf(a - m) + expf(c - m)));
    }
}

// ---------------------------------------------------------------------------
// Inputs (metadata order): X, y, Wx, Wh1, Wh2, b, W_fc, b_fc. Output: float[32].
// ---------------------------------------------------------------------------
extern "C" void kernel_launch(void* const* d_in, const int* in_sizes, int n_in,
                              void* d_out, int out_size)
{
    const float* X    = (const float*)d_in[0];
    const int*   y    = (const int*)  d_in[1];
    const float* Wx   = (const float*)d_in[2];
    const float* Wh1  = (const float*)d_in[3];
    const float* Wh2  = (const float*)d_in[4];
    const float* bias = (const float*)d_in[5];
    const float* W_fc = (const float*)d_in[6];
    const float* b_fc = (const float*)d_in[7];
    float* out = (float*)d_out;

    init_kernel<<<256, 256>>>();

    const int NDIAG = Tc + Fc - 1;  // 287
    for (int d = 0; d < NDIAG; d++) {
        int h_lo = (d > Tc - 1) ? (d - (Tc - 1)) : 0;
        int h_hi = (d < Fc - 1) ? d : (Fc - 1);
        int ncells = h_hi - h_lo + 1;
        diag_kernel<<<dim3(ncells, 4), 320>>>(d, X, Wx, Wh1, Wh2, bias);
    }

    fc_kernel<<<dim3(Tc, Bc), 128>>>(W_fc, b_fc);
    ctc_kernel<<<Bc, 128>>>(y, out);
}

// round 2
// speedup vs baseline: 1.6177x; 1.6177x over previous
#include <cuda_runtime.h>
#include <math.h>

#define Bc   32
#define Tc   256
#define Fc   32
#define HIDc 128
#define ZW   640
#define Vc   101
#define Sc   65
#define LBLc 32
#define NEGF (-1e30f)

#define NCTA 128
#define NTHR 256
#define SH_STRIDE 257
#define SW_FLOATS (8*5*256*2)          // 20480 floats = 80KB
#define SH_FLOATS (64*SH_STRIDE)       // 16448 floats
#define SMEM_BYTES ((SW_FLOATS + SH_FLOATS)*4)

// ---------------------------------------------------------------------------
// Device scratch. Double-buffered row state by diagonal parity.
// ---------------------------------------------------------------------------
__device__ float g_h[2][Fc][Bc][HIDc];
__device__ float g_c[2][Fc][Bc][HIDc];
__device__ float g_feat[Bc][Tc][HIDc];
__device__ float g_logp[Bc][Tc][Vc];
__device__ unsigned g_cnt;
__device__ volatile unsigned g_gen;

__device__ __forceinline__ float sigf(float x) { return 1.0f / (1.0f + expf(-x)); }

__device__ __forceinline__ unsigned long long pack_dup(float x) {
    unsigned long long r;
    asm("mov.b64 %0, {%1, %1};" : "=l"(r) : "f"(x));
    return r;
}
__device__ __forceinline__ unsigned long long pack2f(float lo, float hi) {
    unsigned long long r;
    asm("mov.b64 %0, {%1, %2};" : "=l"(r) : "f"(lo), "f"(hi));
    return r;
}
__device__ __forceinline__ void unpack2f(unsigned long long v, float& lo, float& hi) {
    asm("mov.b64 {%0, %1}, %2;" : "=f"(lo), "=f"(hi) : "l"(v));
}
__device__ __forceinline__ unsigned long long fma2(unsigned long long a,
                                                   unsigned long long b,
                                                   unsigned long long c) {
    unsigned long long d;
    asm("fma.rn.f32x2 %0, %1, %2, %3;" : "=l"(d) : "l"(a), "l"(b), "l"(c));
    return d;
}

__global__ void init_kernel() {
    const int n = 2 * Fc * Bc * HIDc;
    float* ph = &g_h[0][0][0][0];
    float* pc = &g_c[0][0][0][0];
    for (int i = blockIdx.x * blockDim.x + threadIdx.x; i < n;
         i += gridDim.x * blockDim.x) {
        ph[i] = 0.0f;
        pc[i] = 0.0f;
    }
    if (blockIdx.x == 0 && threadIdx.x == 0) { g_cnt = 0; g_gen = 0; }
}

// Grid-wide barrier: sense via monotone generation counter.
__device__ __forceinline__ void gbar() {
    __syncthreads();
    if (threadIdx.x == 0) {
        __threadfence();                       // publish my CTA's writes
        unsigned gen = g_gen;
        if (atomicAdd(&g_cnt, 1u) == NCTA - 1) {
            g_cnt = 0;
            __threadfence();
            g_gen = gen + 1;
        } else {
            while (g_gen == gen) { __nanosleep(32); }
        }
    }
    __syncthreads();
}

// ---------------------------------------------------------------------------
// Persistent MDLSTM wavefront kernel.
// Grid: 128 CTAs = 8 k-blocks x 4 batch-groups x 4 cell-groups.
// CTA owns 80 z-columns (16 k x 5 gates), weights cached in smem forever.
// Threads: 256 = 32 row-pairs x 8 col-groups. Thread -> 2 rows x 2 k-cols,
// all 5 gates in-register -> gates computed in-thread, 1 barrier/diagonal.
// ---------------------------------------------------------------------------
__global__ __launch_bounds__(NTHR, 1)
void mdlstm_persist(const float* __restrict__ X,
                    const float* __restrict__ Wx,
                    const float* __restrict__ Wh1,
                    const float* __restrict__ Wh2,
                    const float* __restrict__ bias)
{
    extern __shared__ float smem[];
    float* s_w = smem;                 // [cg=8][g=5][k=256][2]
    float* s_h = smem + SW_FLOATS;     // [row=64][257]

    const int tid  = threadIdx.x;
    const int bx   = blockIdx.x;
    const int jkb  = bx & 7;           // k-block (16 hidden dims)
    const int bg   = (bx >> 3) & 3;    // batch group (8 batches)
    const int cgid = bx >> 5;          // cell group (8 cells)

    const int cg = tid >> 5;           // col group 0..7 (owns kk = jkb*16+cg*2, +1)
    const int rp = tid & 31;           // row pair base

    // One-time: weights into smem. s_w[((cg*5+g)*256+k)*2+c] = W[k][col]
    for (int i = tid; i < SW_FLOATS; i += NTHR) {
        int c  = i & 1;
        int t1 = i >> 1;
        int k  = t1 & 255;
        int t2 = t1 >> 8;
        int g  = t2 % 5;
        int cgl = t2 / 5;
        int col = g * HIDc + jkb * 16 + cgl * 2 + c;
        s_w[i] = (k < 128) ? Wh1[k * ZW + col] : Wh2[(k - 128) * ZW + col];
    }

    const int kk0 = jkb * 16 + cg * 2;
    float wxl[5], wxh[5], bll[5], blh[5];
#pragma unroll
    for (int g = 0; g < 5; g++) {
        int col = g * HIDc + kk0;
        float2 wv = *(const float2*)&Wx[col];
        float2 bv = *(const float2*)&bias[col];
        wxl[g] = wv.x; wxh[g] = wv.y; bll[g] = bv.x; blh[g] = bv.y;
    }

    const int row0 = rp, row1 = rp + 32;
    const int cell0 = cgid * 8 + (row0 >> 3);
    const int cell1 = cgid * 8 + (row1 >> 3);
    const int b0 = bg * 8 + (row0 & 7);
    const int b1 = bg * 8 + (row1 & 7);

    __syncthreads();

    for (int d = 0; d < Tc + Fc - 1; d++) {
        const int h_lo = (d > Tc - 1) ? d - (Tc - 1) : 0;
        const int h_hi = (d < Fc - 1) ? d : (Fc - 1);
        const int ncells = h_hi - h_lo + 1;
        const int rd = (d + 1) & 1, wr = d & 1;

        // Stage h states: s_h[row][k] : k<128 = h_left, k>=128 = h_up.
        for (int ii = tid; ii < 64 * 64; ii += NTHR) {
            int row = ii >> 6;
            int k4  = (ii & 63) << 2;
            int cell = cgid * 8 + (row >> 3);
            float4 v = make_float4(0.f, 0.f, 0.f, 0.f);
            if (cell < ncells) {
                int hh = h_lo + cell;
                int bb = bg * 8 + (row & 7);
                if (k4 < 128)
                    v = __ldcv((const float4*)&g_h[rd][hh][bb][k4]);
                else if (hh > 0)
                    v = __ldcv((const float4*)&g_h[rd][hh - 1][bb][k4 - 128]);
            }
            float* dst = &s_h[row * SH_STRIDE + k4];
            dst[0] = v.x; dst[1] = v.y; dst[2] = v.z; dst[3] = v.w;
        }
        __syncthreads();

        const int hh0 = h_lo + cell0, hh1 = h_lo + cell1;
        const int w0 = d - hh0, w1 = d - hh1;
        const bool v0 = (cell0 < ncells), v1 = (cell1 < ncells);
        const float xv0 = v0 ? X[b0 * (Tc * Fc) + w0 * Fc + hh0] : 0.f;
        const float xv1 = v1 ? X[b1 * (Tc * Fc) + w1 * Fc + hh1] : 0.f;

        unsigned long long acc0[5], acc1[5];
#pragma unroll
        for (int g = 0; g < 5; g++) {
            acc0[g] = pack2f(fmaf(xv0, wxl[g], bll[g]), fmaf(xv0, wxh[g], blh[g]));
            acc1[g] = pack2f(fmaf(xv1, wxl[g], bll[g]), fmaf(xv1, wxh[g], blh[g]));
        }

        const float* wbase = s_w + cg * 2560;
        const float* h0p = s_h + row0 * SH_STRIDE;
        const float* h1p = s_h + row1 * SH_STRIDE;

#pragma unroll 4
        for (int k = 0; k < 256; k++) {
            unsigned long long hp0 = pack_dup(h0p[k]);
            unsigned long long hp1 = pack_dup(h1p[k]);
#pragma unroll
            for (int g = 0; g < 5; g++) {
                unsigned long long w2 =
                    *(const unsigned long long*)(wbase + g * 512 + k * 2);
                acc0[g] = fma2(w2, hp0, acc0[g]);
                acc1[g] = fma2(w2, hp1, acc1[g]);
            }
        }

        // Gates, fully in-thread (z order: i, g, f1, f2, o).
#pragma unroll
        for (int r = 0; r < 2; r++) {
            const bool vv = r ? v1 : v0;
            if (!vv) continue;
            const int hh = r ? hh1 : hh0;
            const int ww = r ? w1 : w0;
            const int bb = r ? b1 : b0;
            unsigned long long* acc = r ? acc1 : acc0;

            float zi0, zi1, zg0, zg1, zf10, zf11, zf20, zf21, zo0, zo1;
            unpack2f(acc[0], zi0, zi1);
            unpack2f(acc[1], zg0, zg1);
            unpack2f(acc[2], zf10, zf11);
            unpack2f(acc[3], zf20, zf21);
            unpack2f(acc[4], zo0, zo1);

            float2 cl = __ldcv((const float2*)&g_c[rd][hh][bb][kk0]);
            float2 cu = (hh > 0) ? __ldcv((const float2*)&g_c[rd][hh - 1][bb][kk0])
                                 : make_float2(0.f, 0.f);

            float cA = sigf(zf10) * cl.x + sigf(zf20) * cu.x + sigf(zi0) * tanhf(zg0);
            float cB = sigf(zf11) * cl.y + sigf(zf21) * cu.y + sigf(zi1) * tanhf(zg1);
            float hA = sigf(zo0) * tanhf(cA);
            float hB = sigf(zo1) * tanhf(cB);

            *(float2*)&g_c[wr][hh][bb][kk0] = make_float2(cA, cB);
            *(float2*)&g_h[wr][hh][bb][kk0] = make_float2(hA, hB);

            float2* fp = (float2*)&g_feat[bb][ww][kk0];
            if (hh == 0) {
                *fp = make_float2(hA, hB);
            } else {
                float2 f = __ldcv((const float2*)fp);
                *fp = make_float2(f.x + hA, f.y + hB);
            }
        }

        gbar();
    }
}

// ---------------------------------------------------------------------------
// logits = feat @ W_fc + b_fc ; logp = log_softmax(logits)
// ---------------------------------------------------------------------------
__global__ __launch_bounds__(128)
void fc_kernel(const float* __restrict__ W_fc, const float* __restrict__ b_fc)
{
    const int w = blockIdx.x, b = blockIdx.y, tid = threadIdx.x;
    __shared__ float s_f[HIDc];
    __shared__ float red[128];

    s_f[tid] = g_feat[b][w][tid];
    __syncthreads();

    float logit = 0.0f;
    if (tid < Vc) {
        float a = b_fc[tid];
#pragma unroll 4
        for (int k = 0; k < HIDc; k++) a = fmaf(s_f[k], W_fc[k * Vc + tid], a);
        logit = a;
    }

    red[tid] = (tid < Vc) ? logit : -INFINITY;
    __syncthreads();
#pragma unroll
    for (int s = 64; s > 0; s >>= 1) {
        if (tid < s) red[tid] = fmaxf(red[tid], red[tid + s]);
        __syncthreads();
    }
    const float m = red[0];
    __syncthreads();

    red[tid] = (tid < Vc) ? expf(logit - m) : 0.0f;
    __syncthreads();
#pragma unroll
    for (int s = 64; s > 0; s >>= 1) {
        if (tid < s) red[tid] += red[tid + s];
        __syncthreads();
    }
    const float lse = m + logf(red[0]);

    if (tid < Vc) g_logp[b][w][tid] = logit - lse;
}

// ---------------------------------------------------------------------------
// CTC forward (alpha recursion). One block per batch element.
// ---------------------------------------------------------------------------
__global__ __launch_bounds__(128)
void ctc_kernel(const int* __restrict__ y, float* __restrict__ out)
{
    const int b = blockIdx.x, tid = threadIdx.x;
    __shared__ float alpha[Sc];
    __shared__ int   ext[Sc];

    if (tid < Sc) {
        ext[tid] = (tid & 1) ? y[b * LBLc + (tid >> 1)] : (Vc - 1);
    }
    __syncthreads();

    bool sk = false;
    if (tid < Sc) {
        sk = (tid >= 2) && (ext[tid] != (Vc - 1)) && (ext[tid] != ext[tid - 2]);
        float a0;
        if (tid == 0)      a0 = g_logp[b][0][ext[0]];
        else if (tid == 1) a0 = g_logp[b][0][ext[1]];
        else               a0 = NEGF;
        alpha[tid] = a0;
    }
    __syncthreads();

    for (int t = 1; t < Tc; t++) {
        float nv = NEGF;
        if (tid < Sc) {
            float a0 = alpha[tid];
            float a1 = (tid >= 1) ? alpha[tid - 1] : NEGF;
            float a2 = sk ? alpha[tid - 2] : NEGF;
            float m  = fmaxf(a0, fmaxf(a1, a2));
            float lse = m + logf(expf(a0 - m) + expf(a1 - m) + expf(a2 - m));
            nv = lse + g_logp[b][t][ext[tid]];
        }
        __syncthreads();
        if (tid < Sc) alpha[tid] = nv;
        __syncthreads();
    }

    if (tid == 0) {
        float a = alpha[Sc - 1], c = alpha[Sc - 2];
        float m = fmaxf(a, c);
        out[b] = -(m + logf(expf(a - m) + expf(c - m)));
    }
}

// ---------------------------------------------------------------------------
// Inputs: X, y, Wx, Wh1, Wh2, b, W_fc, b_fc. Output: float[32].
// ---------------------------------------------------------------------------
extern "C" void kernel_launch(void* const* d_in, const int* in_sizes, int n_in,
                              void* d_out, int out_size)
{
    const float* X    = (const float*)d_in[0];
    const int*   y    = (const int*)  d_in[1];
    const float* Wx   = (const float*)d_in[2];
    const float* Wh1  = (const float*)d_in[3];
    const float* Wh2  = (const float*)d_in[4];
    const float* bias = (const float*)d_in[5];
    const float* W_fc = (const float*)d_in[6];
    const float* b_fc = (const float*)d_in[7];
    float* out = (float*)d_out;

    static bool attr_set = false;
    if (!attr_set) {
        cudaFuncSetAttribute(mdlstm_persist,
                             cudaFuncAttributeMaxDynamicSharedMemorySize,
                             SMEM_BYTES);
        attr_set = true;
    }

    init_kernel<<<256, 256>>>();
    mdlstm_persist<<<NCTA, NTHR, SMEM_BYTES>>>(X, Wx, Wh1, Wh2, bias);
    fc_kernel<<<dim3(Tc, Bc), 128>>>(W_fc, b_fc);
    ctc_kernel<<<Bc, 128>>>(y, out);
}

// round 3
// speedup vs baseline: 1.6218x; 1.0025x over previous
#include <cuda_runtime.h>
#include <math.h>

#define Bc   32
#define Tc   256
#define Fc   32
#define HIDc 128
#define ZW   640
#define Vc   101
#define Sc   65
#define LBLc 32
#define NEGF (-1e30f)

#define NCTA 128
#define NTHR 256
#define SH_STRIDE 257
#define SW_FLOATS (8*5*256*2)          // 20480 floats = 80KB
#define SH_FLOATS (64*SH_STRIDE)       // 16448 floats
#define SMEM_BYTES ((SW_FLOATS + SH_FLOATS)*4)

// ---------------------------------------------------------------------------
// Device scratch. Double-buffered row state by diagonal parity.
// ---------------------------------------------------------------------------
__device__ float g_h[2][Fc][Bc][HIDc];
__device__ float g_c[2][Fc][Bc][HIDc];
__device__ float g_feat[Bc][Tc][HIDc];
__device__ float g_logp[Bc][Tc][Vc];
__device__ unsigned g_cnt;
__device__ volatile unsigned g_gen;

__device__ __forceinline__ float sigf(float x) { return 1.0f / (1.0f + expf(-x)); }

__device__ __forceinline__ unsigned long long pack_dup(float x) {
    unsigned long long r;
    asm("mov.b64 %0, {%1, %1};" : "=l"(r) : "f"(x));
    return r;
}
__device__ __forceinline__ unsigned long long pack2f(float lo, float hi) {
    unsigned long long r;
    asm("mov.b64 %0, {%1, %2};" : "=l"(r) : "f"(lo), "f"(hi));
    return r;
}
__device__ __forceinline__ void unpack2f(unsigned long long v, float& lo, float& hi) {
    asm("mov.b64 {%0, %1}, %2;" : "=f"(lo), "=f"(hi) : "l"(v));
}
__device__ __forceinline__ unsigned long long fma2(unsigned long long a,
                                                   unsigned long long b,
                                                   unsigned long long c) {
    unsigned long long d;
    asm("fma.rn.f32x2 %0, %1, %2, %3;" : "=l"(d) : "l"(a), "l"(b), "l"(c));
    return d;
}

__global__ void init_kernel() {
    const int n = 2 * Fc * Bc * HIDc;
    float* ph = &g_h[0][0][0][0];
    float* pc = &g_c[0][0][0][0];
    for (int i = blockIdx.x * blockDim.x + threadIdx.x; i < n;
         i += gridDim.x * blockDim.x) {
        ph[i] = 0.0f;
        pc[i] = 0.0f;
    }
    if (blockIdx.x == 0 && threadIdx.x == 0) { g_cnt = 0; g_gen = 0; }
}

// Grid-wide barrier: sense via monotone generation counter.
__device__ __forceinline__ void gbar() {
    __syncthreads();
    if (threadIdx.x == 0) {
        __threadfence();                       // publish my CTA's writes
        unsigned gen = g_gen;
        if (atomicAdd(&g_cnt, 1u) == NCTA - 1) {
            g_cnt = 0;
            __threadfence();
            g_gen = gen + 1;
        } else {
            while (g_gen == gen) { __nanosleep(32); }
        }
    }
    __syncthreads();
}

// ---------------------------------------------------------------------------
// Persistent MDLSTM wavefront kernel.
// Grid: 128 CTAs = 8 k-blocks x 4 batch-groups x 4 cell-groups.
// CTA owns 80 z-columns (16 k x 5 gates), weights cached in smem forever.
// Threads: 256 = 32 row-pairs x 8 col-groups. Thread -> 2 rows x 2 k-cols,
// all 5 gates in-register -> gates computed in-thread, 1 barrier/diagonal.
// ---------------------------------------------------------------------------
__global__ __launch_bounds__(NTHR, 1)
void mdlstm_persist(const float* __restrict__ X,
                    const float* __restrict__ Wx,
                    const float* __restrict__ Wh1,
                    const float* __restrict__ Wh2,
                    const float* __restrict__ bias)
{
    extern __shared__ float smem[];
    float* s_w = smem;                 // [cg=8][g=5][k=256][2]
    float* s_h = smem + SW_FLOATS;     // [row=64][257]

    const int tid  = threadIdx.x;
    const int bx   = blockIdx.x;
    const int jkb  = bx & 7;           // k-block (16 hidden dims)
    const int bg   = (bx >> 3) & 3;    // batch group (8 batches)
    const int cgid = bx >> 5;          // cell group (8 cells)

    const int cg = tid >> 5;           // col group 0..7 (owns kk = jkb*16+cg*2, +1)
    const int rp = tid & 31;           // row pair base

    // One-time: weights into smem. s_w[((cg*5+g)*256+k)*2+c] = W[k][col]
    for (int i = tid; i < SW_FLOATS; i += NTHR) {
        int c  = i & 1;
        int t1 = i >> 1;
        int k  = t1 & 255;
        int t2 = t1 >> 8;
        int g  = t2 % 5;
        int cgl = t2 / 5;
        int col = g * HIDc + jkb * 16 + cgl * 2 + c;
        s_w[i] = (k < 128) ? Wh1[k * ZW + col] : Wh2[(k - 128) * ZW + col];
    }

    const int kk0 = jkb * 16 + cg * 2;
    float wxl[5], wxh[5], bll[5], blh[5];
#pragma unroll
    for (int g = 0; g < 5; g++) {
        int col = g * HIDc + kk0;
        float2 wv = *(const float2*)&Wx[col];
        float2 bv = *(const float2*)&bias[col];
        wxl[g] = wv.x; wxh[g] = wv.y; bll[g] = bv.x; blh[g] = bv.y;
    }

    const int row0 = rp, row1 = rp + 32;
    const int cell0 = cgid * 8 + (row0 >> 3);
    const int cell1 = cgid * 8 + (row1 >> 3);
    const int b0 = bg * 8 + (row0 & 7);
    const int b1 = bg * 8 + (row1 & 7);

    __syncthreads();

    for (int d = 0; d < Tc + Fc - 1; d++) {
        const int h_lo = (d > Tc - 1) ? d - (Tc - 1) : 0;
        const int h_hi = (d < Fc - 1) ? d : (Fc - 1);
        const int ncells = h_hi - h_lo + 1;
        const int rd = (d + 1) & 1, wr = d & 1;

        // Stage h states: s_h[row][k] : k<128 = h_left, k>=128 = h_up.
        for (int ii = tid; ii < 64 * 64; ii += NTHR) {
            int row = ii >> 6;
            int k4  = (ii & 63) << 2;
            int cell = cgid * 8 + (row >> 3);
            float4 v = make_float4(0.f, 0.f, 0.f, 0.f);
            if (cell < ncells) {
                int hh = h_lo + cell;
                int bb = bg * 8 + (row & 7);
                if (k4 < 128)
                    v = __ldcv((const float4*)&g_h[rd][hh][bb][k4]);
                else if (hh > 0)
                    v = __ldcv((const float4*)&g_h[rd][hh - 1][bb][k4 - 128]);
            }
            float* dst = &s_h[row * SH_STRIDE + k4];
            dst[0] = v.x; dst[1] = v.y; dst[2] = v.z; dst[3] = v.w;
        }
        __syncthreads();

        const int hh0 = h_lo + cell0, hh1 = h_lo + cell1;
        const int w0 = d - hh0, w1 = d - hh1;
        const bool v0 = (cell0 < ncells), v1 = (cell1 < ncells);
        const float xv0 = v0 ? X[b0 * (Tc * Fc) + w0 * Fc + hh0] : 0.f;
        const float xv1 = v1 ? X[b1 * (Tc * Fc) + w1 * Fc + hh1] : 0.f;

        unsigned long long acc0[5], acc1[5];
#pragma unroll
        for (int g = 0; g < 5; g++) {
            acc0[g] = pack2f(fmaf(xv0, wxl[g], bll[g]), fmaf(xv0, wxh[g], blh[g]));
            acc1[g] = pack2f(fmaf(xv1, wxl[g], bll[g]), fmaf(xv1, wxh[g], blh[g]));
        }

        const float* wbase = s_w + cg * 2560;
        const float* h0p = s_h + row0 * SH_STRIDE;
        const float* h1p = s_h + row1 * SH_STRIDE;

#pragma unroll 4
        for (int k = 0; k < 256; k++) {
            unsigned long long hp0 = pack_dup(h0p[k]);
            unsigned long long hp1 = pack_dup(h1p[k]);
#pragma unroll
            for (int g = 0; g < 5; g++) {
                unsigned long long w2 =
                    *(const unsigned long long*)(wbase + g * 512 + k * 2);
                acc0[g] = fma2(w2, hp0, acc0[g]);
                acc1[g] = fma2(w2, hp1, acc1[g]);
            }
        }

        // Gates, fully in-thread (z order: i, g, f1, f2, o).
#pragma unroll
        for (int r = 0; r < 2; r++) {
            const bool vv = r ? v1 : v0;
            if (!vv) continue;
            const int hh = r ? hh1 : hh0;
            const int ww = r ? w1 : w0;
            const int bb = r ? b1 : b0;
            unsigned long long* acc = r ? acc1 : acc0;

            float zi0, zi1, zg0, zg1, zf10, zf11, zf20, zf21, zo0, zo1;
            unpack2f(acc[0], zi0, zi1);
            unpack2f(acc[1], zg0, zg1);
            unpack2f(acc[2], zf10, zf11);
            unpack2f(acc[3], zf20, zf21);
            unpack2f(acc[4], zo0, zo1);

            float2 cl = __ldcv((const float2*)&g_c[rd][hh][bb][kk0]);
            float2 cu = (hh > 0) ? __ldcv((const float2*)&g_c[rd][hh - 1][bb][kk0])
                                 : make_float2(0.f, 0.f);

            float cA = sigf(zf10) * cl.x + sigf(zf20) * cu.x + sigf(zi0) * tanhf(zg0);
            float cB = sigf(zf11) * cl.y + sigf(zf21) * cu.y + sigf(zi1) * tanhf(zg1);
            float hA = sigf(zo0) * tanhf(cA);
            float hB = sigf(zo1) * tanhf(cB);

            *(float2*)&g_c[wr][hh][bb][kk0] = make_float2(cA, cB);
            *(float2*)&g_h[wr][hh][bb][kk0] = make_float2(hA, hB);

            float2* fp = (float2*)&g_feat[bb][ww][kk0];
            if (hh == 0) {
                *fp = make_float2(hA, hB);
            } else {
                float2 f = __ldcv((const float2*)fp);
                *fp = make_float2(f.x + hA, f.y + hB);
            }
        }

        gbar();
    }
}

// ---------------------------------------------------------------------------
// logits = feat @ W_fc + b_fc ; logp = log_softmax(logits)
// ---------------------------------------------------------------------------
__global__ __launch_bounds__(128)
void fc_kernel(const float* __restrict__ W_fc, const float* __restrict__ b_fc)
{
    const int w = blockIdx.x, b = blockIdx.y, tid = threadIdx.x;
    __shared__ float s_f[HIDc];
    __shared__ float red[128];

    s_f[tid] = g_feat[b][w][tid];
    __syncthreads();

    float logit = 0.0f;
    if (tid < Vc) {
        float a = b_fc[tid];
#pragma unroll 4
        for (int k = 0; k < HIDc; k++) a = fmaf(s_f[k], W_fc[k * Vc + tid], a);
        logit = a;
    }

    red[tid] = (tid < Vc) ? logit : -INFINITY;
    __syncthreads();
#pragma unroll
    for (int s = 64; s > 0; s >>= 1) {
        if (tid < s) red[tid] = fmaxf(red[tid], red[tid + s]);
        __syncthreads();
    }
    const float m = red[0];
    __syncthreads();

    red[tid] = (tid < Vc) ? expf(logit - m) : 0.0f;
    __syncthreads();
#pragma unroll
    for (int s = 64; s > 0; s >>= 1) {
        if (tid < s) red[tid] += red[tid + s];
        __syncthreads();
    }
    const float lse = m + logf(red[0]);

    if (tid < Vc) g_logp[b][w][tid] = logit - lse;
}

// ---------------------------------------------------------------------------
// CTC forward (alpha recursion). One block per batch element.
// ---------------------------------------------------------------------------
__global__ __launch_bounds__(128)
void ctc_kernel(const int* __restrict__ y, float* __restrict__ out)
{
    const int b = blockIdx.x, tid = threadIdx.x;
    __shared__ float alpha[Sc];
    __shared__ int   ext[Sc];

    if (tid < Sc) {
        ext[tid] = (tid & 1) ? y[b * LBLc + (tid >> 1)] : (Vc - 1);
    }
    __syncthreads();

    bool sk = false;
    if (tid < Sc) {
        sk = (tid >= 2) && (ext[tid] != (Vc - 1)) && (ext[tid] != ext[tid - 2]);
        float a0;
        if (tid == 0)      a0 = g_logp[b][0][ext[0]];
        else if (tid == 1) a0 = g_logp[b][0][ext[1]];
        else               a0 = NEGF;
        alpha[tid] = a0;
    }
    __syncthreads();

    for (int t = 1; t < Tc; t++) {
        float nv = NEGF;
        if (tid < Sc) {
            float a0 = alpha[tid];
            float a1 = (tid >= 1) ? alpha[tid - 1] : NEGF;
            float a2 = sk ? alpha[tid - 2] : NEGF;
            float m  = fmaxf(a0, fmaxf(a1, a2));
            float lse = m + logf(expf(a0 - m) + expf(a1 - m) + expf(a2 - m));
            nv = lse + g_logp[b][t][ext[tid]];
        }
        __syncthreads();
        if (tid < Sc) alpha[tid] = nv;
        __syncthreads();
    }

    if (tid == 0) {
        float a = alpha[Sc - 1], c = alpha[Sc - 2];
        float m = fmaxf(a, c);
        out[b] = -(m + logf(expf(a - m) + expf(c - m)));
    }
}

// ---------------------------------------------------------------------------
// Inputs: X, y, Wx, Wh1, Wh2, b, W_fc, b_fc. Output: float[32].
// ---------------------------------------------------------------------------
extern "C" void kernel_launch(void* const* d_in, const int* in_sizes, int n_in,
                              void* d_out, int out_size)
{
    const float* X    = (const float*)d_in[0];
    const int*   y    = (const int*)  d_in[1];
    const float* Wx   = (const float*)d_in[2];
    const float* Wh1  = (const float*)d_in[3];
    const float* Wh2  = (const float*)d_in[4];
    const float* bias = (const float*)d_in[5];
    const float* W_fc = (const float*)d_in[6];
    const float* b_fc = (const float*)d_in[7];
    float* out = (float*)d_out;

    static bool attr_set = false;
    if (!attr_set) {
        cudaFuncSetAttribute(mdlstm_persist,
                             cudaFuncAttributeMaxDynamicSharedMemorySize,
                             SMEM_BYTES);
        attr_set = true;
    }

    init_kernel<<<256, 256>>>();
    mdlstm_persist<<<NCTA, NTHR, SMEM_BYTES>>>(X, Wx, Wh1, Wh2, bias);
    fc_kernel<<<dim3(Tc, Bc), 128>>>(W_fc, b_fc);
    ctc_kernel<<<Bc, 128>>>(y, out);
}

// round 4
// speedup vs baseline: 1.6269x; 1.0032x over previous
#include <cuda_runtime.h>
#include <math.h>

#define Bc   32
#define Tc   256
#define Fc   32
#define HIDc 128
#define ZW   640
#define Vc   101
#define Sc   65
#define LBLc 32
#define NEGF (-1e30f)

#define NCTA 128
#define NTHR 256
#define SH_STRIDE 257
#define SW_FLOATS (8*5*256*2)          // 20480 floats = 80KB
#define SH_FLOATS (64*SH_STRIDE)       // 16448 floats
#define SMEM_BYTES ((SW_FLOATS + SH_FLOATS)*4)

// ---------------------------------------------------------------------------
// Device scratch. Double-buffered row state by diagonal parity.
// ---------------------------------------------------------------------------
__device__ float g_h[2][Fc][Bc][HIDc];
__device__ float g_c[2][Fc][Bc][HIDc];
__device__ float g_feat[Bc][Tc][HIDc];
__device__ float g_logp[Bc][Tc][Vc];
__device__ unsigned g_cnt;
__device__ volatile unsigned g_gen;

__device__ __forceinline__ float sigf(float x) { return 1.0f / (1.0f + expf(-x)); }

__device__ __forceinline__ unsigned long long pack_dup(float x) {
    unsigned long long r;
    asm("mov.b64 %0, {%1, %1};" : "=l"(r) : "f"(x));
    return r;
}
__device__ __forceinline__ unsigned long long pack2f(float lo, float hi) {
    unsigned long long r;
    asm("mov.b64 %0, {%1, %2};" : "=l"(r) : "f"(lo), "f"(hi));
    return r;
}
__device__ __forceinline__ void unpack2f(unsigned long long v, float& lo, float& hi) {
    asm("mov.b64 {%0, %1}, %2;" : "=f"(lo), "=f"(hi) : "l"(v));
}
__device__ __forceinline__ unsigned long long fma2(unsigned long long a,
                                                   unsigned long long b,
                                                   unsigned long long c) {
    unsigned long long d;
    asm("fma.rn.f32x2 %0, %1, %2, %3;" : "=l"(d) : "l"(a), "l"(b), "l"(c));
    return d;
}

__global__ void init_kernel() {
    const int n = 2 * Fc * Bc * HIDc;
    float* ph = &g_h[0][0][0][0];
    float* pc = &g_c[0][0][0][0];
    for (int i = blockIdx.x * blockDim.x + threadIdx.x; i < n;
         i += gridDim.x * blockDim.x) {
        ph[i] = 0.0f;
        pc[i] = 0.0f;
    }
    if (blockIdx.x == 0 && threadIdx.x == 0) { g_cnt = 0; g_gen = 0; }
}

// Grid-wide barrier: sense via monotone generation counter.
__device__ __forceinline__ void gbar() {
    __syncthreads();
    if (threadIdx.x == 0) {
        __threadfence();                       // publish my CTA's writes
        unsigned gen = g_gen;
        if (atomicAdd(&g_cnt, 1u) == NCTA - 1) {
            g_cnt = 0;
            __threadfence();
            g_gen = gen + 1;
        } else {
            while (g_gen == gen) { __nanosleep(32); }
        }
    }
    __syncthreads();
}

// ---------------------------------------------------------------------------
// Persistent MDLSTM wavefront kernel.
// Grid: 128 CTAs = 8 k-blocks x 4 batch-groups x 4 cell-groups.
// CTA owns 80 z-columns (16 k x 5 gates), weights cached in smem forever.
// Threads: 256 = 32 row-pairs x 8 col-groups. Thread -> 2 rows x 2 k-cols,
// all 5 gates in-register -> gates computed in-thread, 1 barrier/diagonal.
// ---------------------------------------------------------------------------
__global__ __launch_bounds__(NTHR, 1)
void mdlstm_persist(const float* __restrict__ X,
                    const float* __restrict__ Wx,
                    const float* __restrict__ Wh1,
                    const float* __restrict__ Wh2,
                    const float* __restrict__ bias)
{
    extern __shared__ float smem[];
    float* s_w = smem;                 // [cg=8][g=5][k=256][2]
    float* s_h = smem + SW_FLOATS;     // [row=64][257]

    const int tid  = threadIdx.x;
    const int bx   = blockIdx.x;
    const int jkb  = bx & 7;           // k-block (16 hidden dims)
    const int bg   = (bx >> 3) & 3;    // batch group (8 batches)
    const int cgid = bx >> 5;          // cell group (8 cells)

    const int cg = tid >> 5;           // col group 0..7 (owns kk = jkb*16+cg*2, +1)
    const int rp = tid & 31;           // row pair base

    // One-time: weights into smem. s_w[((cg*5+g)*256+k)*2+c] = W[k][col]
    for (int i = tid; i < SW_FLOATS; i += NTHR) {
        int c  = i & 1;
        int t1 = i >> 1;
        int k  = t1 & 255;
        int t2 = t1 >> 8;
        int g  = t2 % 5;
        int cgl = t2 / 5;
        int col = g * HIDc + jkb * 16 + cgl * 2 + c;
        s_w[i] = (k < 128) ? Wh1[k * ZW + col] : Wh2[(k - 128) * ZW + col];
    }

    const int kk0 = jkb * 16 + cg * 2;
    float wxl[5], wxh[5], bll[5], blh[5];
#pragma unroll
    for (int g = 0; g < 5; g++) {
        int col = g * HIDc + kk0;
        float2 wv = *(const float2*)&Wx[col];
        float2 bv = *(const float2*)&bias[col];
        wxl[g] = wv.x; wxh[g] = wv.y; bll[g] = bv.x; blh[g] = bv.y;
    }

    const int row0 = rp, row1 = rp + 32;
    const int cell0 = cgid * 8 + (row0 >> 3);
    const int cell1 = cgid * 8 + (row1 >> 3);
    const int b0 = bg * 8 + (row0 & 7);
    const int b1 = bg * 8 + (row1 & 7);

    __syncthreads();

    for (int d = 0; d < Tc + Fc - 1; d++) {
        const int h_lo = (d > Tc - 1) ? d - (Tc - 1) : 0;
        const int h_hi = (d < Fc - 1) ? d : (Fc - 1);
        const int ncells = h_hi - h_lo + 1;
        const int rd = (d + 1) & 1, wr = d & 1;

        // Stage h states: s_h[row][k] : k<128 = h_left, k>=128 = h_up.
        for (int ii = tid; ii < 64 * 64; ii += NTHR) {
            int row = ii >> 6;
            int k4  = (ii & 63) << 2;
            int cell = cgid * 8 + (row >> 3);
            float4 v = make_float4(0.f, 0.f, 0.f, 0.f);
            if (cell < ncells) {
                int hh = h_lo + cell;
                int bb = bg * 8 + (row & 7);
                if (k4 < 128)
                    v = __ldcv((const float4*)&g_h[rd][hh][bb][k4]);
                else if (hh > 0)
                    v = __ldcv((const float4*)&g_h[rd][hh - 1][bb][k4 - 128]);
            }
            float* dst = &s_h[row * SH_STRIDE + k4];
            dst[0] = v.x; dst[1] = v.y; dst[2] = v.z; dst[3] = v.w;
        }
        __syncthreads();

        const int hh0 = h_lo + cell0, hh1 = h_lo + cell1;
        const int w0 = d - hh0, w1 = d - hh1;
        const bool v0 = (cell0 < ncells), v1 = (cell1 < ncells);
        const float xv0 = v0 ? X[b0 * (Tc * Fc) + w0 * Fc + hh0] : 0.f;
        const float xv1 = v1 ? X[b1 * (Tc * Fc) + w1 * Fc + hh1] : 0.f;

        unsigned long long acc0[5], acc1[5];
#pragma unroll
        for (int g = 0; g < 5; g++) {
            acc0[g] = pack2f(fmaf(xv0, wxl[g], bll[g]), fmaf(xv0, wxh[g], blh[g]));
            acc1[g] = pack2f(fmaf(xv1, wxl[g], bll[g]), fmaf(xv1, wxh[g], blh[g]));
        }

        const float* wbase = s_w + cg * 2560;
        const float* h0p = s_h + row0 * SH_STRIDE;
        const float* h1p = s_h + row1 * SH_STRIDE;

#pragma unroll 4
        for (int k = 0; k < 256; k++) {
            unsigned long long hp0 = pack_dup(h0p[k]);
            unsigned long long hp1 = pack_dup(h1p[k]);
#pragma unroll
            for (int g = 0; g < 5; g++) {
                unsigned long long w2 =
                    *(const unsigned long long*)(wbase + g * 512 + k * 2);
                acc0[g] = fma2(w2, hp0, acc0[g]);
                acc1[g] = fma2(w2, hp1, acc1[g]);
            }
        }

        // Gates, fully in-thread (z order: i, g, f1, f2, o).
#pragma unroll
        for (int r = 0; r < 2; r++) {
            const bool vv = r ? v1 : v0;
            if (!vv) continue;
            const int hh = r ? hh1 : hh0;
            const int ww = r ? w1 : w0;
            const int bb = r ? b1 : b0;
            unsigned long long* acc = r ? acc1 : acc0;

            float zi0, zi1, zg0, zg1, zf10, zf11, zf20, zf21, zo0, zo1;
            unpack2f(acc[0], zi0, zi1);
            unpack2f(acc[1], zg0, zg1);
            unpack2f(acc[2], zf10, zf11);
            unpack2f(acc[3], zf20, zf21);
            unpack2f(acc[4], zo0, zo1);

            float2 cl = __ldcv((const float2*)&g_c[rd][hh][bb][kk0]);
            float2 cu = (hh > 0) ? __ldcv((const float2*)&g_c[rd][hh - 1][bb][kk0])
                                 : make_float2(0.f, 0.f);

            float cA = sigf(zf10) * cl.x + sigf(zf20) * cu.x + sigf(zi0) * tanhf(zg0);
            float cB = sigf(zf11) * cl.y + sigf(zf21) * cu.y + sigf(zi1) * tanhf(zg1);
            float hA = sigf(zo0) * tanhf(cA);
            float hB = sigf(zo1) * tanhf(cB);

            *(float2*)&g_c[wr][hh][bb][kk0] = make_float2(cA, cB);
            *(float2*)&g_h[wr][hh][bb][kk0] = make_float2(hA, hB);

            float2* fp = (float2*)&g_feat[bb][ww][kk0];
            if (hh == 0) {
                *fp = make_float2(hA, hB);
            } else {
                float2 f = __ldcv((const float2*)fp);
                *fp = make_float2(f.x + hA, f.y + hB);
            }
        }

        gbar();
    }
}

// ---------------------------------------------------------------------------
// logits = feat @ W_fc + b_fc ; logp = log_softmax(logits)
// ---------------------------------------------------------------------------
__global__ __launch_bounds__(128)
void fc_kernel(const float* __restrict__ W_fc, const float* __restrict__ b_fc)
{
    const int w = blockIdx.x, b = blockIdx.y, tid = threadIdx.x;
    __shared__ float s_f[HIDc];
    __shared__ float red[128];

    s_f[tid] = g_feat[b][w][tid];
    __syncthreads();

    float logit = 0.0f;
    if (tid < Vc) {
        float a = b_fc[tid];
#pragma unroll 4
        for (int k = 0; k < HIDc; k++) a = fmaf(s_f[k], W_fc[k * Vc + tid], a);
        logit = a;
    }

    red[tid] = (tid < Vc) ? logit : -INFINITY;
    __syncthreads();
#pragma unroll
    for (int s = 64; s > 0; s >>= 1) {
        if (tid < s) red[tid] = fmaxf(red[tid], red[tid + s]);
        __syncthreads();
    }
    const float m = red[0];
    __syncthreads();

    red[tid] = (tid < Vc) ? expf(logit - m) : 0.0f;
    __syncthreads();
#pragma unroll
    for (int s = 64; s > 0; s >>= 1) {
        if (tid < s) red[tid] += red[tid + s];
        __syncthreads();
    }
    const float lse = m + logf(red[0]);

    if (tid < Vc) g_logp[b][w][tid] = logit - lse;
}

// ---------------------------------------------------------------------------
// CTC forward (alpha recursion). One block per batch element.
// ---------------------------------------------------------------------------
__global__ __launch_bounds__(128)
void ctc_kernel(const int* __restrict__ y, float* __restrict__ out)
{
    const int b = blockIdx.x, tid = threadIdx.x;
    __shared__ float alpha[Sc];
    __shared__ int   ext[Sc];

    if (tid < Sc) {
        ext[tid] = (tid & 1) ? y[b * LBLc + (tid >> 1)] : (Vc - 1);
    }
    __syncthreads();

    bool sk = false;
    if (tid < Sc) {
        sk = (tid >= 2) && (ext[tid] != (Vc - 1)) && (ext[tid] != ext[tid - 2]);
        float a0;
        if (tid == 0)      a0 = g_logp[b][0][ext[0]];
        else if (tid == 1) a0 = g_logp[b][0][ext[1]];
        else               a0 = NEGF;
        alpha[tid] = a0;
    }
    __syncthreads();

    for (int t = 1; t < Tc; t++) {
        float nv = NEGF;
        if (tid < Sc) {
            float a0 = alpha[tid];
            float a1 = (tid >= 1) ? alpha[tid - 1] : NEGF;
            float a2 = sk ? alpha[tid - 2] : NEGF;
            float m  = fmaxf(a0, fmaxf(a1, a2));
            float lse = m + logf(expf(a0 - m) + expf(a1 - m) + expf(a2 - m));
            nv = lse + g_logp[b][t][ext[tid]];
        }
        __syncthreads();
        if (tid < Sc) alpha[tid] = nv;
        __syncthreads();
    }

    if (tid == 0) {
        float a = alpha[Sc - 1], c = alpha[Sc - 2];
        float m = fmaxf(a, c);
        out[b] = -(m + logf(expf(a - m) + expf(c - m)));
    }
}

// ---------------------------------------------------------------------------
// Inputs: X, y, Wx, Wh1, Wh2, b, W_fc, b_fc. Output: float[32].
// ---------------------------------------------------------------------------
extern "C" void kernel_launch(void* const* d_in, const int* in_sizes, int n_in,
                              void* d_out, int out_size)
{
    const float* X    = (const float*)d_in[0];
    const int*   y    = (const int*)  d_in[1];
    const float* Wx   = (const float*)d_in[2];
    const float* Wh1  = (const float*)d_in[3];
    const float* Wh2  = (const float*)d_in[4];
    const float* bias = (const float*)d_in[5];
    const float* W_fc = (const float*)d_in[6];
    const float* b_fc = (const float*)d_in[7];
    float* out = (float*)d_out;

    static bool attr_set = false;
    if (!attr_set) {
        cudaFuncSetAttribute(mdlstm_persist,
                             cudaFuncAttributeMaxDynamicSharedMemorySize,
                             SMEM_BYTES);
        attr_set = true;
    }

    init_kernel<<<256, 256>>>();
    mdlstm_persist<<<NCTA, NTHR, SMEM_BYTES>>>(X, Wx, Wh1, Wh2, bias);
    fc_kernel<<<dim3(Tc, Bc), 128>>>(W_fc, b_fc);
    ctc_kernel<<<Bc, 128>>>(y, out);
}